// round 16
// baseline (speedup 1.0000x reference)
#include <cuda_runtime.h>

// YOLOv1 loss, GB300. pred/target [8192,7,7,30] f32 -> 4 f32 scalars.
// yolo_part: one block = TWO batches (256 threads), float4 streaming loads.

#define ELEMS 1470
#define MAXB  8192

// per-block partials (2 batches each): x=noobj, y=cls, z=coord, w=obj
__device__ float4 g_partials[MAXB / 2];
__device__ float4 g_stage[16];

__global__ void __launch_bounds__(256)
yolo_part(const float* __restrict__ pred, const float* __restrict__ targ)
{
    int tid = threadIdx.x;

    // 98 cells = 2 batches x 49. Box channels staged raw; class channels
    // reduced to per-pair d^2 sums at load time.
    __shared__ __align__(8) float spb[98][10];
    __shared__ __align__(8) float stb[98][10];
    __shared__ __align__(8) float sd2[98][10];
    __shared__ float px1[196], py1[196], px2[196], py2[196];
    __shared__ float qx1[196], qy1[196], qx2[196], qy2[196];
    __shared__ int   objlist[2][98];
    __shared__ int   cnt[2];
    __shared__ float red[4][8];

    if (tid < 2) cnt[tid] = 0;

    // 2-batch span: base = blk*11760 bytes, 16B aligned -> float4 legal.
    size_t base = (size_t)blockIdx.x * (2 * ELEMS);
    const float4* p4 = reinterpret_cast<const float4*>(pred + base);
    const float4* t4 = reinterpret_cast<const float4*>(targ + base);

    // 735 float4 per tensor. Thread t<240: cp0=t/15, k=t%15 (computed once).
    // j = g*240 + t  ->  cell-pair cp = g*16 + cp0 (240 = 16*15), role k:
    //  k=0,1   : cellA ch 4k..4k+3        box
    //  k=2     : cellA ch8,9 box + ch10,11 class (slot 0)
    //  k=3..6  : cellA class slots 2k-5, 2k-4
    //  k=7     : cellA ch28,29 class (slot 9) + cellB ch0,1 box
    //  k=8,9   : cellB ch 4k-30..4k-27    box
    //  k=10..14: cellB class slots 2k-20, 2k-19
    int cp0 = 0, kk = 0;
    bool active = (tid < 240);
    if (active) { cp0 = tid / 15; kk = tid - cp0 * 15; }

    #pragma unroll
    for (int g = 0; g < 4; g++) {
        int j, cp;
        bool run;
        if (g < 3) { run = active;    j = g * 240 + tid; cp = g * 16 + cp0; }
        else       { run = (tid < 15); j = 720 + tid;     cp = 48; }
        if (run) {
            int k  = (g < 3) ? kk : tid;   // for g==3, tid<15 so tid%15==tid
            int cA = 2 * cp;
            int cB = cA + 1;
            float4 pv = p4[j];
            float4 tv = t4[j];
            if (k < 2) {
                int ch = 4 * k;
                *reinterpret_cast<float2*>(&spb[cA][ch])     = make_float2(pv.x, pv.y);
                *reinterpret_cast<float2*>(&spb[cA][ch + 2]) = make_float2(pv.z, pv.w);
                *reinterpret_cast<float2*>(&stb[cA][ch])     = make_float2(tv.x, tv.y);
                *reinterpret_cast<float2*>(&stb[cA][ch + 2]) = make_float2(tv.z, tv.w);
            } else if (k == 2) {
                *reinterpret_cast<float2*>(&spb[cA][8]) = make_float2(pv.x, pv.y);
                *reinterpret_cast<float2*>(&stb[cA][8]) = make_float2(tv.x, tv.y);
                float d1 = pv.z - tv.z, d2 = pv.w - tv.w;
                sd2[cA][0] = d1 * d1 + d2 * d2;
            } else if (k <= 6) {
                float d1 = pv.x - tv.x, d2 = pv.y - tv.y;
                float d3 = pv.z - tv.z, d4 = pv.w - tv.w;
                sd2[cA][2 * k - 5] = d1 * d1 + d2 * d2;
                sd2[cA][2 * k - 4] = d3 * d3 + d4 * d4;
            } else if (k == 7) {
                float d1 = pv.x - tv.x, d2 = pv.y - tv.y;
                sd2[cA][9] = d1 * d1 + d2 * d2;
                *reinterpret_cast<float2*>(&spb[cB][0]) = make_float2(pv.z, pv.w);
                *reinterpret_cast<float2*>(&stb[cB][0]) = make_float2(tv.z, tv.w);
            } else if (k <= 9) {
                int ch = 4 * k - 30;   // 2 or 6
                *reinterpret_cast<float2*>(&spb[cB][ch])     = make_float2(pv.x, pv.y);
                *reinterpret_cast<float2*>(&spb[cB][ch + 2]) = make_float2(pv.z, pv.w);
                *reinterpret_cast<float2*>(&stb[cB][ch])     = make_float2(tv.x, tv.y);
                *reinterpret_cast<float2*>(&stb[cB][ch + 2]) = make_float2(tv.z, tv.w);
            } else {
                float d1 = pv.x - tv.x, d2 = pv.y - tv.y;
                float d3 = pv.z - tv.z, d4 = pv.w - tv.w;
                sd2[cB][2 * k - 20] = d1 * d1 + d2 * d2;
                sd2[cB][2 * k - 19] = d3 * d3 + d4 * d4;
            }
        }
    }
    __syncthreads();

    float a0 = 0.0f, a1 = 0.0f, a2 = 0.0f, a3 = 0.0f;  // noobj, cls, coord, obj

    // per-box xyxy + per-batch compacted obj-box lists (196 boxes)
    if (tid < 196) {
        int cell = tid >> 1;
        int off  = (tid & 1) * 5;
        {
            float cx = spb[cell][off],     cy = spb[cell][off + 1];
            float w  = spb[cell][off + 2], h  = spb[cell][off + 3];
            px1[tid] = cx - w * 0.5f; py1[tid] = cy - h * 0.5f;
            px2[tid] = cx + w * 0.5f; py2[tid] = cy + h * 0.5f;
        }
        {
            float cx = stb[cell][off],     cy = stb[cell][off + 1];
            float w  = stb[cell][off + 2], h  = stb[cell][off + 3];
            qx1[tid] = cx - w * 0.5f; qy1[tid] = cy - h * 0.5f;
            qx2[tid] = cx + w * 0.5f; qy2[tid] = cy + h * 0.5f;
        }
        if (stb[cell][4] > 0.0f) {
            int h = (cell >= 49) ? 1 : 0;
            objlist[h][atomicAdd(&cnt[h], 1)] = tid;
        }
    }
    __syncthreads();

    // per-cell: noobj confidence loss OR class loss
    if (tid < 98) {
        if (stb[tid][4] == 0.0f) {
            float d4 = spb[tid][4] - stb[tid][4];
            float d9 = spb[tid][9] - stb[tid][9];
            a0 = d4 * d4 + d9 * d9;
        } else {
            const float2* c2 = reinterpret_cast<const float2*>(sd2[tid]);
            float s = 0.0f;
            #pragma unroll
            for (int q = 0; q < 5; q++) {
                float2 v = c2[q];
                s += v.x + v.y;
            }
            a1 = s;
        }
    }

    // cmask: (max_iou != 0) <=> exists overlapping obj pred box (same batch).
    if (tid < 196 && stb[tid >> 1][4] > 0.0f) {
        int h = ((tid >> 1) >= 49) ? 1 : 0;
        float X1 = qx1[tid], Y1 = qy1[tid], X2 = qx2[tid], Y2 = qy2[tid];
        bool hit = false;
        int n = cnt[h];
        for (int ii = 0; ii < n; ii++) {
            int j = objlist[h][ii];
            float iw = fminf(px2[j], X2) - fmaxf(px1[j], X1);
            float ih = fminf(py2[j], Y2) - fmaxf(py1[j], Y1);
            if (iw > 0.0f && ih > 0.0f) { hit = true; break; }
        }
        if (hit) {
            int cell = tid >> 1;
            int off  = (tid & 1) * 5;
            float dx = spb[cell][off]     - stb[cell][off];
            float dy = spb[cell][off + 1] - stb[cell][off + 1];
            float dw = sqrtf(spb[cell][off + 2]) - sqrtf(stb[cell][off + 2]);
            float dh = sqrtf(spb[cell][off + 3]) - sqrtf(stb[cell][off + 3]);
            a2 = dx * dx + dy * dy + dw * dw + dh * dh;
            float dc = spb[cell][off + 4] - stb[cell][off + 4];
            a3 = dc * dc;
        }
    }

    // block reduce 4 accumulators across 256 threads
    #pragma unroll
    for (int o = 16; o > 0; o >>= 1) {
        a0 += __shfl_down_sync(0xffffffffu, a0, o);
        a1 += __shfl_down_sync(0xffffffffu, a1, o);
        a2 += __shfl_down_sync(0xffffffffu, a2, o);
        a3 += __shfl_down_sync(0xffffffffu, a3, o);
    }
    int warp = tid >> 5, lane = tid & 31;
    if (lane == 0) {
        red[0][warp] = a0; red[1][warp] = a1; red[2][warp] = a2; red[3][warp] = a3;
    }
    __syncthreads();
    if (tid == 0) {
        float4 r = make_float4(0.f, 0.f, 0.f, 0.f);
        #pragma unroll
        for (int w = 0; w < 8; w++) {
            r.x += red[0][w]; r.y += red[1][w];
            r.z += red[2][w]; r.w += red[3][w];
        }
        g_partials[blockIdx.x] = r;
    }
}

// Stage 1: 16 blocks x 256 threads over 4096 partials.
__global__ void __launch_bounds__(256)
yolo_red1(void)
{
    int tid = threadIdx.x;
    int idx = blockIdx.x * 256 + tid;
    float4 v = g_partials[idx];
    float s0 = v.x, s1 = v.y, s2 = v.z, s3 = v.w;
    #pragma unroll
    for (int o = 16; o > 0; o >>= 1) {
        s0 += __shfl_down_sync(0xffffffffu, s0, o);
        s1 += __shfl_down_sync(0xffffffffu, s1, o);
        s2 += __shfl_down_sync(0xffffffffu, s2, o);
        s3 += __shfl_down_sync(0xffffffffu, s3, o);
    }
    __shared__ float sm[8][4];
    int warp = tid >> 5, lane = tid & 31;
    if (lane == 0) {
        sm[warp][0] = s0; sm[warp][1] = s1; sm[warp][2] = s2; sm[warp][3] = s3;
    }
    __syncthreads();
    if (tid == 0) {
        float t0 = 0, t1 = 0, t2 = 0, t3 = 0;
        #pragma unroll
        for (int w = 0; w < 8; w++) {
            t0 += sm[w][0]; t1 += sm[w][1]; t2 += sm[w][2]; t3 += sm[w][3];
        }
        g_stage[blockIdx.x] = make_float4(t0, t1, t2, t3);
    }
}

// Stage 2: one warp over 16 stage results, finalize.
__global__ void __launch_bounds__(32)
yolo_red2(int B, float* __restrict__ out)
{
    int tid = threadIdx.x;
    float s0 = 0, s1 = 0, s2 = 0, s3 = 0;
    if (tid < 16) {
        float4 v = g_stage[tid];
        s0 = v.x; s1 = v.y; s2 = v.z; s3 = v.w;
    }
    #pragma unroll
    for (int o = 16; o > 0; o >>= 1) {
        s0 += __shfl_down_sync(0xffffffffu, s0, o);
        s1 += __shfl_down_sync(0xffffffffu, s1, o);
        s2 += __shfl_down_sync(0xffffffffu, s2, o);
        s3 += __shfl_down_sync(0xffffffffu, s3, o);
    }
    if (tid == 0) {
        double invB  = 1.0 / (double)B;
        double cls   = (double)s1 * invB;
        double objl  = ((double)s3 + (double)s0 * 0.5) * invB;
        double coord = (double)s2 * 5.0 * invB;
        out[0] = (float)(cls + objl + coord);
        out[1] = (float)cls;
        out[2] = (float)objl;
        out[3] = (float)coord;
    }
}

extern "C" void kernel_launch(void* const* d_in, const int* in_sizes, int n_in,
                              void* d_out, int out_size)
{
    const float* pred = (const float*)d_in[0];
    const float* targ = (const float*)d_in[1];
    float* out = (float*)d_out;
    int B = in_sizes[0] / ELEMS;
    if (B > MAXB) B = MAXB;

    yolo_part<<<B / 2, 256>>>(pred, targ);
    yolo_red1<<<16, 256>>>();
    yolo_red2<<<1, 32>>>(B, out);
}